// round 15
// baseline (speedup 1.0000x reference)
#include <cuda_runtime.h>
#include <cstdint>

#define Bb   32
#define Ss   512
#define INP  512
#define Hh   1024
#define Gg   3072
#define Ll   4
#define RS   (Bb*Ss)

// persistent recurrence kernel config
#define NB   128          // blocks (<=148 SMs, all resident -> flag-wait safe)
#define NT   256          // 8 warps
#define RPB  24           // gate rows per block (3072/128), divisible by 3
#define UPB  8            // hidden units per block
#define WST  1028         // W smem row stride (words)
#define RST  25           // partial row stride

// ---------------- device scratch ----------------
__device__ float g_gates[(size_t)RS * Gg];      // 192 MiB
__device__ float g_y0[(size_t)RS * Hh];
__device__ float g_y1[(size_t)RS * Hh];
__device__ float g_hbufHi[2 * Bb * Hh];         // ping-pong recurrent h, tf32 hi bits
__device__ float g_hbufLo[2 * Bb * Hh];         // tf32 lo bits
__device__ float g_wihHi[(size_t)Gg * INP + 3 * (size_t)Gg * Hh];  // pre-split hi
__device__ float g_wihLo[(size_t)Gg * INP + 3 * (size_t)Gg * Hh];  // pre-split lo
__device__ float g_whhp[(size_t)Ll * Gg * Hh];
__device__ float g_bp[Ll * Gg];
__device__ unsigned g_flags[8];                 // per-k-slice publish counters

// ---------------- helpers ----------------
__device__ __forceinline__ unsigned f2tf(float f) {
    unsigned u;
    asm("cvt.rna.tf32.f32 %0, %1;" : "=r"(u) : "f"(f));
    return u;
}
__device__ __forceinline__ void split_tf(float x, unsigned& hi, unsigned& lo) {
    hi = f2tf(x);
    lo = f2tf(x - __uint_as_float(hi));
}
__device__ __forceinline__ void split4(float4 f, uint4& h, uint4& l) {
    split_tf(f.x, h.x, l.x); split_tf(f.y, h.y, l.y);
    split_tf(f.z, h.z, l.z); split_tf(f.w, h.w, l.w);
}
__device__ __forceinline__ void mma_tf32(float c[4],
                                         unsigned a0, unsigned a1, unsigned a2, unsigned a3,
                                         unsigned b0, unsigned b1) {
    asm volatile(
        "mma.sync.aligned.m16n8k8.row.col.f32.tf32.tf32.f32 "
        "{%0,%1,%2,%3}, {%4,%5,%6,%7}, {%8,%9}, {%0,%1,%2,%3};\n"
        : "+f"(c[0]), "+f"(c[1]), "+f"(c[2]), "+f"(c[3])
        : "r"(a0), "r"(a1), "r"(a2), "r"(a3), "r"(b0), "r"(b1));
}
__device__ __forceinline__ float sigf(float x) { return 1.0f / (1.0f + expf(-x)); }

// ---------------- reorder kernel 1: W_ih all layers, pre-split hi/lo ----------------
__global__ void k_reorder_ih(const float4* __restrict__ w0, const float4* __restrict__ wr,
                             float4* __restrict__ hi4, float4* __restrict__ lo4) {
    const int L0   = Gg * (INP / 4);
    const int LPER = Gg * (Hh / 4);
    const int total = L0 + 3 * LPER;
    for (int i = blockIdx.x * blockDim.x + threadIdx.x; i < total; i += gridDim.x * blockDim.x) {
        float4 s;
        if (i < L0) {
            int np = i / (INP / 4), k = i % (INP / 4);
            int h = np / 3, g = np - h * 3;
            s = w0[(size_t)(g * Hh + h) * (INP / 4) + k];
        } else {
            int j = i - L0;
            int l = j / LPER, r = j - l * LPER;
            int np = r / (Hh / 4), k = r % (Hh / 4);
            int h = np / 3, g = np - h * 3;
            s = wr[(size_t)l * LPER + (size_t)(g * Hh + h) * (Hh / 4) + k];
        }
        uint4 h4, l4;
        split4(s, h4, l4);
        hi4[i] = make_float4(__uint_as_float(h4.x), __uint_as_float(h4.y),
                             __uint_as_float(h4.z), __uint_as_float(h4.w));
        lo4[i] = make_float4(__uint_as_float(l4.x), __uint_as_float(l4.y),
                             __uint_as_float(l4.z), __uint_as_float(l4.w));
    }
}

// ---------------- reorder kernel 2: W_hh all layers (fp32) + biases ----------------
__global__ void k_reorder_hh(const float4* __restrict__ w0, const float4* __restrict__ wr,
                             const float* __restrict__ b0, const float* __restrict__ br,
                             float4* __restrict__ dst, float* __restrict__ bp) {
    const int tid0 = blockIdx.x * blockDim.x + threadIdx.x;
    if (tid0 < Ll * Gg) {
        int l = tid0 / Gg, j = tid0 - l * Gg;
        int h = j / 3, g = j - h * 3;
        const float* sb = (l == 0) ? b0 : (br + (size_t)(l - 1) * Gg);
        bp[tid0] = sb[g * Hh + h];
    }
    const int LPER = Gg * (Hh / 4);
    const int total = Ll * LPER;
    for (int i = tid0; i < total; i += gridDim.x * blockDim.x) {
        int l = i / LPER, r = i - l * LPER;
        int np = r / (Hh / 4), k = r % (Hh / 4);
        int h = np / 3, g = np - h * 3;
        const float4* src = (l == 0) ? w0 : (wr + (size_t)(l - 1) * LPER);
        dst[i] = src[(size_t)(g * Hh + h) * (Hh / 4) + k];
    }
}

// ---------------- input projection GEMM (3xTF32, SMEM-free, LDG.128 k16 frags) ----------------
// Slot map (tq,pos) -> k = k0 + 4*tq + pos on BOTH operands: each fragment pair
// (even mma: .x/.y, odd mma: .z/.w) comes from one float4/uint4 LDG covering k16.
__global__ __launch_bounds__(256) void gemm_input(const float* __restrict__ X,
                                                  const float* __restrict__ WHi,
                                                  const float* __restrict__ WLo,
                                                  const float* __restrict__ bias,
                                                  float* __restrict__ out,
                                                  int K) {
    if (blockIdx.x == 0 && blockIdx.y == 0 && threadIdx.x < 8) {
        g_flags[threadIdx.x] = 0;   // reset slice flags for the next lstm_layer
    }

    const int tid  = threadIdx.x;
    const int warp = tid >> 5, lane = tid & 31;
    const int gq = lane >> 2, tq = lane & 3;
    const int wm = (warp & 1) * 64;
    const int wn = (warp >> 1) * 32;
    const int rowBase = blockIdx.y * 128;
    const int colBase = blockIdx.x * 128;

    float C[4][4][4];
#pragma unroll
    for (int mf = 0; mf < 4; mf++)
#pragma unroll
        for (int nf = 0; nf < 4; nf++)
#pragma unroll
            for (int q = 0; q < 4; q++) C[mf][nf][q] = 0.0f;

    const float* Ab = X + (size_t)(rowBase + wm + gq) * K + 4 * tq;
    const size_t bro = (size_t)(colBase + wn + gq) * K + 4 * tq;
    const float* BHb = WHi + bro;
    const float* BLb = WLo + bro;

    for (int k0 = 0; k0 < K; k0 += 16) {
        // ---- load + split A fragments (4 mf x 2 rows, float4 each) ----
        uint4 aH0[4], aH1[4], aL0[4], aL1[4];
#pragma unroll
        for (int mf = 0; mf < 4; mf++) {
            float4 f0 = __ldg((const float4*)(Ab + (size_t)(mf * 16) * K + k0));
            float4 f1 = __ldg((const float4*)(Ab + (size_t)(mf * 16 + 8) * K + k0));
            split4(f0, aH0[mf], aL0[mf]);
            split4(f1, aH1[mf], aL1[mf]);
        }
        // ---- load B fragments (4 nf, pre-split hi/lo, uint4 each) ----
        uint4 bH[4], bL[4];
#pragma unroll
        for (int nf = 0; nf < 4; nf++) {
            bH[nf] = __ldg((const uint4*)(BHb + (size_t)(nf * 8) * K + k0));
            bL[nf] = __ldg((const uint4*)(BLb + (size_t)(nf * 8) * K + k0));
        }

        // even slots (.x/.y): HH, LH, HL passes
#pragma unroll
        for (int mf = 0; mf < 4; mf++)
#pragma unroll
            for (int nf = 0; nf < 4; nf++)
                mma_tf32(C[mf][nf], aH0[mf].x, aH1[mf].x, aH0[mf].y, aH1[mf].y,
                         bH[nf].x, bH[nf].y);
#pragma unroll
        for (int mf = 0; mf < 4; mf++)
#pragma unroll
            for (int nf = 0; nf < 4; nf++)
                mma_tf32(C[mf][nf], aL0[mf].x, aL1[mf].x, aL0[mf].y, aL1[mf].y,
                         bH[nf].x, bH[nf].y);
#pragma unroll
        for (int mf = 0; mf < 4; mf++)
#pragma unroll
            for (int nf = 0; nf < 4; nf++)
                mma_tf32(C[mf][nf], aH0[mf].x, aH1[mf].x, aH0[mf].y, aH1[mf].y,
                         bL[nf].x, bL[nf].y);
        // odd slots (.z/.w): HH, LH, HL passes
#pragma unroll
        for (int mf = 0; mf < 4; mf++)
#pragma unroll
            for (int nf = 0; nf < 4; nf++)
                mma_tf32(C[mf][nf], aH0[mf].z, aH1[mf].z, aH0[mf].w, aH1[mf].w,
                         bH[nf].z, bH[nf].w);
#pragma unroll
        for (int mf = 0; mf < 4; mf++)
#pragma unroll
            for (int nf = 0; nf < 4; nf++)
                mma_tf32(C[mf][nf], aL0[mf].z, aL1[mf].z, aL0[mf].w, aL1[mf].w,
                         bH[nf].z, bH[nf].w);
#pragma unroll
        for (int mf = 0; mf < 4; mf++)
#pragma unroll
            for (int nf = 0; nf < 4; nf++)
                mma_tf32(C[mf][nf], aH0[mf].z, aH1[mf].z, aH0[mf].w, aH1[mf].w,
                         bL[nf].z, bL[nf].w);
    }

#pragma unroll
    for (int mf = 0; mf < 4; mf++) {
#pragma unroll
        for (int nf = 0; nf < 4; nf++) {
            int r0 = rowBase + wm + mf * 16 + gq;
            int c0 = colBase + wn + nf * 8 + 2 * tq;
            float bi0 = bias[c0], bi1 = bias[c0 + 1];
            *(float2*)&out[(size_t)r0 * Gg + c0] =
                make_float2(C[mf][nf][0] + bi0, C[mf][nf][1] + bi1);
            *(float2*)&out[(size_t)(r0 + 8) * Gg + c0] =
                make_float2(C[mf][nf][2] + bi0, C[mf][nf][3] + bi1);
        }
    }
}

// ---------------- persistent per-layer recurrence (3xTF32, pipelined j-loop) ----------------
// R8 slice-flag sync. The j-loop now prefetches j+1's A (global h) and B (smem W)
// fragments into registers before issuing j's mmas, hiding L2/LDS latency behind
// a full mma group. Per-C mma order unchanged -> bit-identical.
__global__ __launch_bounds__(NT, 1) void lstm_layer(const float* __restrict__ gates,
                                                    const float* __restrict__ W,
                                                    float* __restrict__ y,
                                                    float* __restrict__ hf,
                                                    float* __restrict__ cf) {
    extern __shared__ unsigned sm[];
    unsigned* WHi = sm;                         // RPB x WST
    unsigned* WLo = sm + RPB * WST;             // RPB x WST
    float*    Rsm = (float*)(sm + 2 * RPB * WST);  // 8 x 32 x RST

    const int tid  = threadIdx.x;
    const int warp = tid >> 5, lane = tid & 31;
    const int gq = lane >> 2, tq = lane & 3;
    const int kw = warp;                 // 0..7 k-slice of 128
    const int blk = blockIdx.x;
    const int npBase = blk * RPB;
    const int hBase  = blk * UPB;
    const int eb = tid >> 3;             // epilogue batch
    const int eu = tid & 7;              // epilogue unit
    unsigned* myflag = &g_flags[blk >> 4];

    // --- load + pre-split W slice to SMEM once per layer ---
    {
        const float4* Wp = (const float4*)(W + (size_t)npBase * Hh);
        for (int i = tid; i < RPB * Hh / 4; i += NT) {
            int r  = i >> 8;
            int c4 = i & 255;
            uint4 h4, l4;
            split4(Wp[i], h4, l4);
            *(uint4*)&WHi[r * WST + c4 * 4] = h4;
            *(uint4*)&WLo[r * WST + c4 * 4] = l4;
        }
    }
    __syncthreads();

    float creg = 0.0f;
    const float* gpt = gates + (size_t)eb * Ss * Gg + npBase + 3 * eu;
    const int colb = kw * 128 + 4 * tq;  // this thread's 16B slot base within k

    float gi = __ldg(gpt), gg = __ldg(gpt + 1), go = __ldg(gpt + 2);

    for (int t = 0; t < Ss; t++) {
        // prefetch next step's gates (overlaps flag wait + mma)
        float ngi = 0.f, ngg = 0.f, ngo = 0.f;
        if (t + 1 < Ss) {
            const float* gp = gpt + (size_t)(t + 1) * Gg;
            ngi = __ldg(gp); ngg = __ldg(gp + 1); ngo = __ldg(gp + 2);
        }

        if (t > 0) {
            // wait for all 16 producers of this warp's k-slice to publish h(t-1)
            {
                const unsigned target = 16u * (unsigned)t;
                unsigned v;
                do {
                    asm volatile("ld.acquire.gpu.u32 %0, [%1];"
                                 : "=r"(v) : "l"(&g_flags[kw]) : "memory");
                } while (v < target);
            }

            float C[2][3][4];
#pragma unroll
            for (int mf = 0; mf < 2; mf++)
#pragma unroll
                for (int nf = 0; nf < 3; nf++)
#pragma unroll
                    for (int q = 0; q < 4; q++) C[mf][nf][q] = 0.0f;

            const float* hbH = g_hbufHi + ((t - 1) & 1) * Bb * Hh + gq * Hh + colb;
            const float* hbL = g_hbufLo + ((t - 1) & 1) * Bb * Hh + gq * Hh + colb;

            // preload j=0 fragments
            uint4 aH[4], aL[4], bH[3], bL[3];
#pragma unroll
            for (int i = 0; i < 4; i++) {
                aH[i] = __ldg((const uint4*)(hbH + i * 8 * Hh));
                aL[i] = __ldg((const uint4*)(hbL + i * 8 * Hh));
            }
#pragma unroll
            for (int nf = 0; nf < 3; nf++) {
                const int n0 = nf * 8 + gq;
                bH[nf] = *(const uint4*)&WHi[n0 * WST + colb];
                bL[nf] = *(const uint4*)&WLo[n0 * WST + colb];
            }

#pragma unroll 2
            for (int j = 0; j < 8; j++) {
                // prefetch j+1 fragments (overlaps the mma group below)
                uint4 naH[4], naL[4], nbH[3], nbL[3];
                if (j < 7) {
                    const int jn = 16 * (j + 1);
#pragma unroll
                    for (int i = 0; i < 4; i++) {
                        naH[i] = __ldg((const uint4*)(hbH + i * 8 * Hh + jn));
                        naL[i] = __ldg((const uint4*)(hbL + i * 8 * Hh + jn));
                    }
#pragma unroll
                    for (int nf = 0; nf < 3; nf++) {
                        const int n0 = nf * 8 + gq;
                        nbH[nf] = *(const uint4*)&WHi[n0 * WST + colb + jn];
                        nbL[nf] = *(const uint4*)&WLo[n0 * WST + colb + jn];
                    }
                }

                // mma group j (order per accumulator identical to R8)
#pragma unroll
                for (int nf = 0; nf < 3; nf++) {
#pragma unroll
                    for (int mf = 0; mf < 2; mf++) {
                        const uint4 x0 = aH[2 * mf], x1 = aH[2 * mf + 1];
                        const uint4 z0 = aL[2 * mf], z1 = aL[2 * mf + 1];
                        mma_tf32(C[mf][nf], x0.x, x1.x, x0.y, x1.y, bH[nf].x, bH[nf].y);
                        mma_tf32(C[mf][nf], z0.x, z1.x, z0.y, z1.y, bH[nf].x, bH[nf].y);
                        mma_tf32(C[mf][nf], x0.x, x1.x, x0.y, x1.y, bL[nf].x, bL[nf].y);
                        mma_tf32(C[mf][nf], x0.z, x1.z, x0.w, x1.w, bH[nf].z, bH[nf].w);
                        mma_tf32(C[mf][nf], z0.z, z1.z, z0.w, z1.w, bH[nf].z, bH[nf].w);
                        mma_tf32(C[mf][nf], x0.z, x1.z, x0.w, x1.w, bL[nf].z, bL[nf].w);
                    }
                }

                if (j < 7) {
#pragma unroll
                    for (int i = 0; i < 4; i++) { aH[i] = naH[i]; aL[i] = naL[i]; }
#pragma unroll
                    for (int nf = 0; nf < 3; nf++) { bH[nf] = nbH[nf]; bL[nf] = nbL[nf]; }
                }
            }

            // dump k-split partials (couples all warps' waits -> ping-pong safety)
#pragma unroll
            for (int mf = 0; mf < 2; mf++)
#pragma unroll
                for (int nf = 0; nf < 3; nf++) {
                    int rrow = mf * 16 + gq;
                    int rcol = nf * 8 + 2 * tq;
                    float* p  = &Rsm[(kw * 32 + rrow) * RST + rcol];
                    p[0] = C[mf][nf][0]; p[1] = C[mf][nf][1];
                    float* p2 = &Rsm[(kw * 32 + rrow + 8) * RST + rcol];
                    p2[0] = C[mf][nf][2]; p2[1] = C[mf][nf][3];
                }
            __syncthreads();
        }

        // fused CEC activation (thread owns (batch eb, unit eu); c in reg)
        {
            float iv = gi, gv = gg, ov = go;
            if (t > 0) {
#pragma unroll
                for (int k2 = 0; k2 < 8; k2++) {
                    const float* rr = &Rsm[(k2 * 32 + eb) * RST + 3 * eu];
                    iv += rr[0]; gv += rr[1]; ov += rr[2];
                }
            }
            creg += sigf(iv) * tanhf(gv);
            float h = sigf(ov) * tanhf(creg);
            const int hidx = hBase + eu;
            unsigned hh, hl;
            split_tf(h, hh, hl);
            const size_t o = (size_t)(t & 1) * Bb * Hh + (size_t)eb * Hh + hidx;
            g_hbufHi[o] = __uint_as_float(hh);
            g_hbufLo[o] = __uint_as_float(hl);
            y[((size_t)eb * Ss + t) * Hh + hidx] = h;
            if (t == Ss - 1) {
                if (hf) hf[eb * Hh + hidx] = h;
                if (cf) cf[eb * Hh + hidx] = creg;
            }
        }
        gi = ngi; gg = ngg; go = ngo;

        // publish this block's slice contribution for step t (one red per block)
        __syncthreads();
        if (tid == 0 && t < Ss - 1) {
            __threadfence();
            asm volatile("red.release.gpu.global.add.u32 [%0], %1;"
                         :: "l"(myflag), "r"(1u) : "memory");
        }
    }
}

// ---------------- host ----------------
extern "C" void kernel_launch(void* const* d_in, const int* in_sizes, int n_in,
                              void* d_out, int out_size) {
    const float* x         = (const float*)d_in[0];
    const float* w_ih0     = (const float*)d_in[1];
    const float* w_hh0     = (const float*)d_in[2];
    const float* b0        = (const float*)d_in[3];
    const float* w_ih_rest = (const float*)d_in[4];
    const float* w_hh_rest = (const float*)d_in[5];
    const float* b_rest    = (const float*)d_in[6];
    float* out = (float*)d_out;

    float *gates, *y0, *y1, *wihHi, *wihLo, *whhp, *bp;
    cudaGetSymbolAddress((void**)&gates, g_gates);
    cudaGetSymbolAddress((void**)&y0, g_y0);
    cudaGetSymbolAddress((void**)&y1, g_y1);
    cudaGetSymbolAddress((void**)&wihHi, g_wihHi);
    cudaGetSymbolAddress((void**)&wihLo, g_wihLo);
    cudaGetSymbolAddress((void**)&whhp, g_whhp);
    cudaGetSymbolAddress((void**)&bp, g_bp);

    const int SMEMB_L = (2 * RPB * WST + 8 * 32 * RST) * 4;       // 222976 B
    cudaFuncSetAttribute(lstm_layer, cudaFuncAttributeMaxDynamicSharedMemorySize, SMEMB_L);

    k_reorder_ih<<<1024, 256>>>((const float4*)w_ih0, (const float4*)w_ih_rest,
                                (float4*)wihHi, (float4*)wihLo);
    k_reorder_hh<<<1024, 256>>>((const float4*)w_hh0, (const float4*)w_hh_rest,
                                b0, b_rest, (float4*)whhp, bp);

    const float* layin[Ll] = {x, y0, y1, y0};
    float* layout_[Ll]     = {y0, y1, y0, out};
    const bool write_states = (out_size >= RS * Hh + 2 * Ll * Bb * Hh);

    const size_t ihOff[Ll] = {0,
                              (size_t)Gg * INP,
                              (size_t)Gg * INP + (size_t)Gg * Hh,
                              (size_t)Gg * INP + 2 * (size_t)Gg * Hh};

    for (int l = 0; l < Ll; l++) {
        int K = (l == 0) ? INP : Hh;
        gemm_input<<<dim3(24, 128), 256>>>(layin[l],
                                           wihHi + ihOff[l],
                                           wihLo + ihOff[l],
                                           bp + (size_t)l * Gg, gates, K);

        float* hf = write_states ? (out + (size_t)RS * Hh + (size_t)l * Bb * Hh) : nullptr;
        float* cf = write_states ? (out + (size_t)RS * Hh + (size_t)Ll * Bb * Hh + (size_t)l * Bb * Hh) : nullptr;
        lstm_layer<<<NB, NT, SMEMB_L>>>(gates, whhp + (size_t)l * Gg * Hh, layout_[l], hf, cf);
    }
}

// round 16
// speedup vs baseline: 1.1006x; 1.1006x over previous
#include <cuda_runtime.h>
#include <cstdint>

#define Bb   32
#define Ss   512
#define INP  512
#define Hh   1024
#define Gg   3072
#define Ll   4
#define RS   (Bb*Ss)

// persistent recurrence kernel config
#define NB   128          // lstm blocks (<=148 SMs; wave-1 resident -> flag-wait safe)
#define NT   256
#define RPB  24
#define UPB  8
#define WST  1028
#define RST  25
#define NGOV 768          // fused gemm blocks (s-group 0: 32 row tiles x 24 col tiles)

// ---------------- device scratch ----------------
__device__ float g_gates0[(size_t)RS * Gg];     // 192 MiB (layers 0,2)
__device__ float g_gates1[(size_t)RS * Gg];     // 192 MiB (layers 1,3)
__device__ float g_y0[(size_t)RS * Hh];
__device__ float g_y1[(size_t)RS * Hh];
__device__ float g_hbufHi[2 * Bb * Hh];
__device__ float g_hbufLo[2 * Bb * Hh];
__device__ float g_wihHi[(size_t)Gg * INP + 3 * (size_t)Gg * Hh];
__device__ float g_wihLo[(size_t)Gg * INP + 3 * (size_t)Gg * Hh];
__device__ float g_whhp[(size_t)Ll * Gg * Hh];
__device__ float g_bp[Ll * Gg];
__device__ unsigned g_flags[9];   // [0..7] per-slice monotonic counters, [8] step progress

// ---------------- helpers ----------------
__device__ __forceinline__ unsigned f2tf(float f) {
    unsigned u;
    asm("cvt.rna.tf32.f32 %0, %1;" : "=r"(u) : "f"(f));
    return u;
}
__device__ __forceinline__ void split_tf(float x, unsigned& hi, unsigned& lo) {
    hi = f2tf(x);
    lo = f2tf(x - __uint_as_float(hi));
}
__device__ __forceinline__ void split4(float4 f, uint4& h, uint4& l) {
    split_tf(f.x, h.x, l.x); split_tf(f.y, h.y, l.y);
    split_tf(f.z, h.z, l.z); split_tf(f.w, h.w, l.w);
}
__device__ __forceinline__ void mma_tf32(float c[4],
                                         unsigned a0, unsigned a1, unsigned a2, unsigned a3,
                                         unsigned b0, unsigned b1) {
    asm volatile(
        "mma.sync.aligned.m16n8k8.row.col.f32.tf32.tf32.f32 "
        "{%0,%1,%2,%3}, {%4,%5,%6,%7}, {%8,%9}, {%0,%1,%2,%3};\n"
        : "+f"(c[0]), "+f"(c[1]), "+f"(c[2]), "+f"(c[3])
        : "r"(a0), "r"(a1), "r"(a2), "r"(a3), "r"(b0), "r"(b1));
}
__device__ __forceinline__ float sigf(float x) { return 1.0f / (1.0f + expf(-x)); }

// ---------------- reorder kernel 1: W_ih all layers, pre-split hi/lo ----------------
__global__ void k_reorder_ih(const float4* __restrict__ w0, const float4* __restrict__ wr,
                             float4* __restrict__ hi4, float4* __restrict__ lo4) {
    const int L0   = Gg * (INP / 4);
    const int LPER = Gg * (Hh / 4);
    const int total = L0 + 3 * LPER;
    for (int i = blockIdx.x * blockDim.x + threadIdx.x; i < total; i += gridDim.x * blockDim.x) {
        float4 s;
        if (i < L0) {
            int np = i / (INP / 4), k = i % (INP / 4);
            int h = np / 3, g = np - h * 3;
            s = w0[(size_t)(g * Hh + h) * (INP / 4) + k];
        } else {
            int j = i - L0;
            int l = j / LPER, r = j - l * LPER;
            int np = r / (Hh / 4), k = r % (Hh / 4);
            int h = np / 3, g = np - h * 3;
            s = wr[(size_t)l * LPER + (size_t)(g * Hh + h) * (Hh / 4) + k];
        }
        uint4 h4, l4;
        split4(s, h4, l4);
        hi4[i] = make_float4(__uint_as_float(h4.x), __uint_as_float(h4.y),
                             __uint_as_float(h4.z), __uint_as_float(h4.w));
        lo4[i] = make_float4(__uint_as_float(l4.x), __uint_as_float(l4.y),
                             __uint_as_float(l4.z), __uint_as_float(l4.w));
    }
}

// ---------------- reorder kernel 2: W_hh all layers (fp32) + biases ----------------
__global__ void k_reorder_hh(const float4* __restrict__ w0, const float4* __restrict__ wr,
                             const float* __restrict__ b0, const float* __restrict__ br,
                             float4* __restrict__ dst, float* __restrict__ bp) {
    const int tid0 = blockIdx.x * blockDim.x + threadIdx.x;
    if (tid0 < Ll * Gg) {
        int l = tid0 / Gg, j = tid0 - l * Gg;
        int h = j / 3, g = j - h * 3;
        const float* sb = (l == 0) ? b0 : (br + (size_t)(l - 1) * Gg);
        bp[tid0] = sb[g * Hh + h];
    }
    const int LPER = Gg * (Hh / 4);
    const int total = Ll * LPER;
    for (int i = tid0; i < total; i += gridDim.x * blockDim.x) {
        int l = i / LPER, r = i - l * LPER;
        int np = r / (Hh / 4), k = r % (Hh / 4);
        int h = np / 3, g = np - h * 3;
        const float4* src = (l == 0) ? w0 : (wr + (size_t)(l - 1) * LPER);
        dst[i] = src[(size_t)(g * Hh + h) * (Hh / 4) + k];
    }
}

// ---------------- gemm body (R13: 3xTF32, SMEM-free direct-LDG frags) ----------------
__device__ __forceinline__ void gemm_body(const float* __restrict__ X,
                                          const float* __restrict__ WHi,
                                          const float* __restrict__ WLo,
                                          const float* __restrict__ bias,
                                          float* __restrict__ out,
                                          int K, int rowBase, int colBase,
                                          unsigned waitTarget) {
    if (waitTarget) {
        if (threadIdx.x == 0) {
            unsigned v;
            do {
                asm volatile("ld.acquire.gpu.u32 %0, [%1];"
                             : "=r"(v) : "l"(&g_flags[8]) : "memory");
            } while (v < waitTarget);
        }
        __syncthreads();
    }

    const int tid  = threadIdx.x;
    const int warp = tid >> 5, lane = tid & 31;
    const int gq = lane >> 2, tq = lane & 3;
    const int wm = (warp & 1) * 64;
    const int wn = (warp >> 1) * 32;

    float C[4][4][4];
#pragma unroll
    for (int mf = 0; mf < 4; mf++)
#pragma unroll
        for (int nf = 0; nf < 4; nf++)
#pragma unroll
            for (int q = 0; q < 4; q++) C[mf][nf][q] = 0.0f;

    const float* Ab = X + (size_t)(rowBase + wm + gq) * K + 2 * tq;
    const size_t bro = (size_t)(colBase + wn + gq) * K + 2 * tq;
    const float* BHb = WHi + bro;
    const float* BLb = WLo + bro;

    for (int k0 = 0; k0 < K; k0 += 8) {
        uint2 aH0[4], aH1[4], aL0[4], aL1[4];
#pragma unroll
        for (int mf = 0; mf < 4; mf++) {
            float2 f0 = __ldg((const float2*)(Ab + (size_t)(mf * 16) * K + k0));
            float2 f1 = __ldg((const float2*)(Ab + (size_t)(mf * 16 + 8) * K + k0));
            split_tf(f0.x, aH0[mf].x, aL0[mf].x);
            split_tf(f0.y, aH0[mf].y, aL0[mf].y);
            split_tf(f1.x, aH1[mf].x, aL1[mf].x);
            split_tf(f1.y, aH1[mf].y, aL1[mf].y);
        }
        uint2 bH[4], bL[4];
#pragma unroll
        for (int nf = 0; nf < 4; nf++) {
            bH[nf] = __ldg((const uint2*)(BHb + (size_t)(nf * 8) * K + k0));
            bL[nf] = __ldg((const uint2*)(BLb + (size_t)(nf * 8) * K + k0));
        }
#pragma unroll
        for (int mf = 0; mf < 4; mf++)
#pragma unroll
            for (int nf = 0; nf < 4; nf++)
                mma_tf32(C[mf][nf], aH0[mf].x, aH1[mf].x, aH0[mf].y, aH1[mf].y,
                         bH[nf].x, bH[nf].y);
#pragma unroll
        for (int mf = 0; mf < 4; mf++)
#pragma unroll
            for (int nf = 0; nf < 4; nf++)
                mma_tf32(C[mf][nf], aL0[mf].x, aL1[mf].x, aL0[mf].y, aL1[mf].y,
                         bH[nf].x, bH[nf].y);
#pragma unroll
        for (int mf = 0; mf < 4; mf++)
#pragma unroll
            for (int nf = 0; nf < 4; nf++)
                mma_tf32(C[mf][nf], aH0[mf].x, aH1[mf].x, aH0[mf].y, aH1[mf].y,
                         bL[nf].x, bL[nf].y);
    }

#pragma unroll
    for (int mf = 0; mf < 4; mf++) {
#pragma unroll
        for (int nf = 0; nf < 4; nf++) {
            int r0 = rowBase + wm + mf * 16 + gq;
            int c0 = colBase + wn + nf * 8 + 2 * tq;
            float bi0 = bias[c0], bi1 = bias[c0 + 1];
            *(float2*)&out[(size_t)r0 * Gg + c0] =
                make_float2(C[mf][nf][0] + bi0, C[mf][nf][1] + bi1);
            *(float2*)&out[(size_t)(r0 + 8) * Gg + c0] =
                make_float2(C[mf][nf][2] + bi0, C[mf][nf][3] + bi1);
        }
    }
}

// ---------------- lstm body (R8 inner loop; monotonic flags; no threadfence) ----------------
__device__ __forceinline__ void lstm_body(unsigned* sm,
                                          const float* __restrict__ gates,
                                          const float* __restrict__ W,
                                          float* __restrict__ y,
                                          float* __restrict__ hf,
                                          float* __restrict__ cf,
                                          unsigned Lbase) {
    unsigned* WHi = sm;
    unsigned* WLo = sm + RPB * WST;
    float*    Rsm = (float*)(sm + 2 * RPB * WST);

    const int tid  = threadIdx.x;
    const int warp = tid >> 5, lane = tid & 31;
    const int gq = lane >> 2, tq = lane & 3;
    const int kw = warp;
    const int blk = blockIdx.x;
    const int npBase = blk * RPB;
    const int hBase  = blk * UPB;
    const int eb = tid >> 3;
    const int eu = tid & 7;
    unsigned* myflag = &g_flags[blk >> 4];

    {
        const float4* Wp = (const float4*)(W + (size_t)npBase * Hh);
        for (int i = tid; i < RPB * Hh / 4; i += NT) {
            int r  = i >> 8;
            int c4 = i & 255;
            uint4 h4, l4;
            split4(Wp[i], h4, l4);
            *(uint4*)&WHi[r * WST + c4 * 4] = h4;
            *(uint4*)&WLo[r * WST + c4 * 4] = l4;
        }
    }
    __syncthreads();

    float creg = 0.0f;
    const float* gpt = gates + (size_t)eb * Ss * Gg + npBase + 3 * eu;
    const int colb = kw * 128 + 4 * tq;

    float gi = __ldg(gpt), gg = __ldg(gpt + 1), go = __ldg(gpt + 2);

    for (int t = 0; t < Ss; t++) {
        float ngi = 0.f, ngg = 0.f, ngo = 0.f;
        if (t + 1 < Ss) {
            const float* gp = gpt + (size_t)(t + 1) * Gg;
            ngi = __ldg(gp); ngg = __ldg(gp + 1); ngo = __ldg(gp + 2);
        }

        if (t > 0) {
            {
                const unsigned target = 16u * (Lbase + (unsigned)t);
                unsigned v;
                do {
                    asm volatile("ld.acquire.gpu.u32 %0, [%1];"
                                 : "=r"(v) : "l"(&g_flags[kw]) : "memory");
                } while (v < target);
            }

            float C[2][3][4];
#pragma unroll
            for (int mf = 0; mf < 2; mf++)
#pragma unroll
                for (int nf = 0; nf < 3; nf++)
#pragma unroll
                    for (int q = 0; q < 4; q++) C[mf][nf][q] = 0.0f;

            const float* hbH = g_hbufHi + ((t - 1) & 1) * Bb * Hh + gq * Hh + colb;
            const float* hbL = g_hbufLo + ((t - 1) & 1) * Bb * Hh + gq * Hh + colb;

#pragma unroll 2
            for (int j = 0; j < 8; j++) {
                const int jc = 16 * j;
                uint4 aH[4], aL[4];
#pragma unroll
                for (int i = 0; i < 4; i++) {
                    aH[i] = __ldg((const uint4*)(hbH + i * 8 * Hh + jc));
                    aL[i] = __ldg((const uint4*)(hbL + i * 8 * Hh + jc));
                }
#pragma unroll
                for (int nf = 0; nf < 3; nf++) {
                    const int n0 = nf * 8 + gq;
                    uint4 bH = *(const uint4*)&WHi[n0 * WST + colb + jc];
                    uint4 bL = *(const uint4*)&WLo[n0 * WST + colb + jc];
#pragma unroll
                    for (int mf = 0; mf < 2; mf++) {
                        const uint4 x0 = aH[2 * mf], x1 = aH[2 * mf + 1];
                        const uint4 z0 = aL[2 * mf], z1 = aL[2 * mf + 1];
                        mma_tf32(C[mf][nf], x0.x, x1.x, x0.y, x1.y, bH.x, bH.y);
                        mma_tf32(C[mf][nf], z0.x, z1.x, z0.y, z1.y, bH.x, bH.y);
                        mma_tf32(C[mf][nf], x0.x, x1.x, x0.y, x1.y, bL.x, bL.y);
                        mma_tf32(C[mf][nf], x0.z, x1.z, x0.w, x1.w, bH.z, bH.w);
                        mma_tf32(C[mf][nf], z0.z, z1.z, z0.w, z1.w, bH.z, bH.w);
                        mma_tf32(C[mf][nf], x0.z, x1.z, x0.w, x1.w, bL.z, bL.w);
                    }
                }
            }

#pragma unroll
            for (int mf = 0; mf < 2; mf++)
#pragma unroll
                for (int nf = 0; nf < 3; nf++) {
                    int rrow = mf * 16 + gq;
                    int rcol = nf * 8 + 2 * tq;
                    float* p  = &Rsm[(kw * 32 + rrow) * RST + rcol];
                    p[0] = C[mf][nf][0]; p[1] = C[mf][nf][1];
                    float* p2 = &Rsm[(kw * 32 + rrow + 8) * RST + rcol];
                    p2[0] = C[mf][nf][2]; p2[1] = C[mf][nf][3];
                }
            __syncthreads();
        }

        {
            float iv = gi, gv = gg, ov = go;
            if (t > 0) {
#pragma unroll
                for (int k2 = 0; k2 < 8; k2++) {
                    const float* rr = &Rsm[(k2 * 32 + eb) * RST + 3 * eu];
                    iv += rr[0]; gv += rr[1]; ov += rr[2];
                }
            }
            creg += sigf(iv) * tanhf(gv);
            float h = sigf(ov) * tanhf(creg);
            const int hidx = hBase + eu;
            unsigned hh, hl;
            split_tf(h, hh, hl);
            const size_t o = (size_t)(t & 1) * Bb * Hh + (size_t)eb * Hh + hidx;
            g_hbufHi[o] = __uint_as_float(hh);
            g_hbufLo[o] = __uint_as_float(hl);
            y[((size_t)eb * Ss + t) * Hh + hidx] = h;
            if (t == Ss - 1) {
                if (hf) hf[eb * Hh + hidx] = h;
                if (cf) cf[eb * Hh + hidx] = creg;
            }
        }
        gi = ngi; gg = ngg; go = ngo;

        // publish every step: slice flag (hbuf/y sync) + global progress.
        // release is cumulative over the block's prior stores (bar.sync HB).
        __syncthreads();
        if (tid == 0) {
            asm volatile("red.release.gpu.global.add.u32 [%0], %1;"
                         :: "l"(myflag), "r"(1u) : "memory");
            asm volatile("red.release.gpu.global.add.u32 [%0], %1;"
                         :: "l"(&g_flags[8]), "r"(1u) : "memory");
        }
    }
}

// ---------------- standalone gemm (layer 0 + post-lstm remainders) ----------------
__global__ __launch_bounds__(256) void gemm_std(const float* __restrict__ X,
                                                const float* __restrict__ WHi,
                                                const float* __restrict__ WLo,
                                                const float* __restrict__ bias,
                                                float* __restrict__ out,
                                                int K, int sgStart) {
    const int sg = sgStart + blockIdx.y / 32;
    const int b  = blockIdx.y % 32;
    const int rowBase = (b * 4 + sg) * 128;
    gemm_body(X, WHi, WLo, bias, out, K, rowBase, blockIdx.x * 128, 0u);
}

// ---------------- fused: lstm(layer l) + overlapped gemm s-group 0 (layer l+1) ----------------
__global__ __launch_bounds__(NT, 1) void fused_lstm_gemm(
    const float* __restrict__ gates, const float* __restrict__ Whh,
    float* __restrict__ y, float* __restrict__ hf, float* __restrict__ cf,
    unsigned Lbase,
    const float* __restrict__ X2, const float* __restrict__ WHi2,
    const float* __restrict__ WLo2, const float* __restrict__ bias2,
    float* __restrict__ out2, unsigned waitTarget) {
    extern __shared__ unsigned sm[];
    if (blockIdx.x < NB) {
        lstm_body(sm, gates, Whh, y, hf, cf, Lbase);
    } else if (X2) {
        const int gid = blockIdx.x - NB;        // 0..767
        const int col = gid % 24;
        const int b   = gid / 24;               // 0..31 -> s-group 0 tiles
        gemm_body(X2, WHi2, WLo2, bias2, out2, Hh, b * 512, col * 128, waitTarget);
    }
}

// ---------------- host ----------------
extern "C" void kernel_launch(void* const* d_in, const int* in_sizes, int n_in,
                              void* d_out, int out_size) {
    const float* x         = (const float*)d_in[0];
    const float* w_ih0     = (const float*)d_in[1];
    const float* w_hh0     = (const float*)d_in[2];
    const float* b0        = (const float*)d_in[3];
    const float* w_ih_rest = (const float*)d_in[4];
    const float* w_hh_rest = (const float*)d_in[5];
    const float* b_rest    = (const float*)d_in[6];
    float* out = (float*)d_out;

    float *gb0, *gb1, *y0, *y1, *wihHi, *wihLo, *whhp, *bp;
    unsigned* flags;
    cudaGetSymbolAddress((void**)&gb0, g_gates0);
    cudaGetSymbolAddress((void**)&gb1, g_gates1);
    cudaGetSymbolAddress((void**)&y0, g_y0);
    cudaGetSymbolAddress((void**)&y1, g_y1);
    cudaGetSymbolAddress((void**)&wihHi, g_wihHi);
    cudaGetSymbolAddress((void**)&wihLo, g_wihLo);
    cudaGetSymbolAddress((void**)&whhp, g_whhp);
    cudaGetSymbolAddress((void**)&bp, g_bp);
    cudaGetSymbolAddress((void**)&flags, g_flags);

    const int SMEMB_L = (2 * RPB * WST + 8 * 32 * RST) * 4;   // 222976 B
    cudaFuncSetAttribute(fused_lstm_gemm, cudaFuncAttributeMaxDynamicSharedMemorySize, SMEMB_L);

    cudaMemsetAsync(flags, 0, 9 * sizeof(unsigned));
    k_reorder_ih<<<1024, 256>>>((const float4*)w_ih0, (const float4*)w_ih_rest,
                                (float4*)wihHi, (float4*)wihLo);
    k_reorder_hh<<<1024, 256>>>((const float4*)w_hh0, (const float4*)w_hh_rest,
                                b0, b_rest, (float4*)whhp, bp);

    const float* layin[Ll] = {x, y0, y1, y0};
    float* layout_[Ll]     = {y0, y1, y0, out};
    float* gbuf[2]         = {gb0, gb1};
    const bool write_states = (out_size >= RS * Hh + 2 * Ll * Bb * Hh);

    const size_t ihOff[Ll] = {0,
                              (size_t)Gg * INP,
                              (size_t)Gg * INP + (size_t)Gg * Hh,
                              (size_t)Gg * INP + 2 * (size_t)Gg * Hh};

    // layer-0 input gemm (full, no wait)
    gemm_std<<<dim3(24, 128), 256>>>(x, wihHi, wihLo, bp, gb0, INP, 0);

    for (int l = 0; l < Ll; l++) {
        float* hf = write_states ? (out + (size_t)RS * Hh + (size_t)l * Bb * Hh) : nullptr;
        float* cf = write_states ? (out + (size_t)RS * Hh + (size_t)Ll * Bb * Hh + (size_t)l * Bb * Hh) : nullptr;
        const unsigned Lbase = (unsigned)(l * Ss);

        if (l < Ll - 1) {
            // fused: lstm(l) + gemm(l+1) s-group 0 (needs lstm step 128)
            const unsigned wt = 128u * (Lbase + 128u);
            fused_lstm_gemm<<<NB + NGOV, NT, SMEMB_L>>>(
                gbuf[l & 1], whhp + (size_t)l * Gg * Hh, layout_[l], hf, cf, Lbase,
                layout_[l], wihHi + ihOff[l + 1], wihLo + ihOff[l + 1],
                bp + (size_t)(l + 1) * Gg, gbuf[(l + 1) & 1], wt);
            // remainder: s-groups 1..3 (data fully ready)
            gemm_std<<<dim3(24, 96), 256>>>(layout_[l],
                                            wihHi + ihOff[l + 1], wihLo + ihOff[l + 1],
                                            bp + (size_t)(l + 1) * Gg, gbuf[(l + 1) & 1],
                                            Hh, 1);
        } else {
            fused_lstm_gemm<<<NB, NT, SMEMB_L>>>(
                gbuf[l & 1], whhp + (size_t)l * Gg * Hh, layout_[l], hf, cf, Lbase,
                nullptr, nullptr, nullptr, nullptr, nullptr, 0u);
        }
    }
}